// round 1
// baseline (speedup 1.0000x reference)
#include <cuda_runtime.h>

#define N_NODES 50000
#define N_EDGES 800000

// ---------------- scratch (static __device__, no runtime allocation) ----------------
__device__ float g_Q[N_NODES * 128];
__device__ float g_K[N_NODES * 128];
__device__ float g_V[N_NODES * 128];
__device__ int   g_row_off[N_NODES + 1];
__device__ int   g_cnt[N_NODES];      // counts, then scatter cursors
__device__ int   g_eidx[N_EDGES];

// ---------------- QKV GEMM: C[z] = h @ W[z] + b[z], z in {Q,K,V} ----------------
// BM=64, BN=128, BK=16, 256 threads, 4x8 microtile.
__global__ void __launch_bounds__(256) gemm_qkv(
    const float* __restrict__ h,
    const float* __restrict__ Wq, const float* __restrict__ bq,
    const float* __restrict__ Wk, const float* __restrict__ bk,
    const float* __restrict__ Wv, const float* __restrict__ bv)
{
    const float* W; const float* bias; float* C;
    int z = blockIdx.z;
    if (z == 0)      { W = Wq; bias = bq; C = g_Q; }
    else if (z == 1) { W = Wk; bias = bk; C = g_K; }
    else             { W = Wv; bias = bv; C = g_V; }

    __shared__ float As[16][64];    // [k][m]
    __shared__ float Bs[16][128];   // [k][n]

    const int t    = threadIdx.x;
    const int row0 = blockIdx.x * 64;
    const int tidx = t & 15;        // col group (8 cols each)
    const int tidy = t >> 4;        // row group (4 rows each)

    float acc[4][8];
    #pragma unroll
    for (int i = 0; i < 4; i++)
        #pragma unroll
        for (int j = 0; j < 8; j++) acc[i][j] = 0.f;

    const int a_row = t >> 2;         // 0..63
    const int a_k   = (t & 3) * 4;    // 0,4,8,12
    const int b_row = t >> 5;         // 0..7
    const int b_col = (t & 31) * 4;   // 0..124

    for (int k0 = 0; k0 < 128; k0 += 16) {
        float4 av = make_float4(0.f, 0.f, 0.f, 0.f);
        int gr = row0 + a_row;
        if (gr < N_NODES)
            av = *reinterpret_cast<const float4*>(&h[gr * 128 + k0 + a_k]);
        As[a_k + 0][a_row] = av.x;
        As[a_k + 1][a_row] = av.y;
        As[a_k + 2][a_row] = av.z;
        As[a_k + 3][a_row] = av.w;

        float4 bv0 = *reinterpret_cast<const float4*>(&W[(k0 + b_row) * 128 + b_col]);
        float4 bv1 = *reinterpret_cast<const float4*>(&W[(k0 + 8 + b_row) * 128 + b_col]);
        *reinterpret_cast<float4*>(&Bs[b_row][b_col])     = bv0;
        *reinterpret_cast<float4*>(&Bs[b_row + 8][b_col]) = bv1;
        __syncthreads();

        #pragma unroll
        for (int k = 0; k < 16; k++) {
            float4 a4  = *reinterpret_cast<const float4*>(&As[k][tidy * 4]);
            float4 b40 = *reinterpret_cast<const float4*>(&Bs[k][tidx * 8]);
            float4 b41 = *reinterpret_cast<const float4*>(&Bs[k][tidx * 8 + 4]);
            float aa[4] = {a4.x, a4.y, a4.z, a4.w};
            float bb[8] = {b40.x, b40.y, b40.z, b40.w, b41.x, b41.y, b41.z, b41.w};
            #pragma unroll
            for (int i = 0; i < 4; i++)
                #pragma unroll
                for (int j = 0; j < 8; j++)
                    acc[i][j] += aa[i] * bb[j];
        }
        __syncthreads();
    }

    #pragma unroll
    for (int i = 0; i < 4; i++) {
        int gr = row0 + tidy * 4 + i;
        if (gr >= N_NODES) continue;
        #pragma unroll
        for (int j = 0; j < 8; j += 4) {
            int col = tidx * 8 + j;
            float4 o;
            o.x = acc[i][j + 0] + bias[col + 0];
            o.y = acc[i][j + 1] + bias[col + 1];
            o.z = acc[i][j + 2] + bias[col + 2];
            o.w = acc[i][j + 3] + bias[col + 3];
            *reinterpret_cast<float4*>(&C[gr * 128 + col]) = o;
        }
    }
}

// ---------------- CSR build ----------------
__global__ void zero_cnt_kernel()
{
    int i = blockIdx.x * blockDim.x + threadIdx.x;
    if (i < N_NODES) g_cnt[i] = 0;
}

__global__ void count_kernel(const int* __restrict__ dst)
{
    int e = blockIdx.x * blockDim.x + threadIdx.x;
    if (e < N_EDGES) atomicAdd(&g_cnt[dst[e]], 1);
}

// single-block scan over 50000 counts -> exclusive offsets (+ cursor copy)
__global__ void __launch_bounds__(1024) scan_kernel()
{
    __shared__ int sm[1024];
    const int t  = threadIdx.x;
    const int CH = (N_NODES + 1023) / 1024;   // 49
    int beg = t * CH;
    int end = beg + CH; if (end > N_NODES) end = N_NODES;

    int sum = 0;
    for (int i = beg; i < end; i++) sum += g_cnt[i];
    sm[t] = sum;
    __syncthreads();

    // Hillis-Steele inclusive scan
    for (int d = 1; d < 1024; d <<= 1) {
        int v = (t >= d) ? sm[t - d] : 0;
        __syncthreads();
        sm[t] += v;
        __syncthreads();
    }

    int run = (t == 0) ? 0 : sm[t - 1];
    for (int i = beg; i < end; i++) {
        int c = g_cnt[i];
        g_row_off[i] = run;
        g_cnt[i]     = run;   // cursor for scatter
        run += c;
    }
    if (t == 1023) g_row_off[N_NODES] = sm[1023];
}

__global__ void scatter_kernel(const int* __restrict__ dst)
{
    int e = blockIdx.x * blockDim.x + threadIdx.x;
    if (e < N_EDGES) {
        int p = atomicAdd(&g_cnt[dst[e]], 1);
        g_eidx[p] = e;
    }
}

// ---------------- aggregation: one warp per dst node ----------------
// lane l owns columns 4l..4l+3; quad (l>>2) owns one head (D=16).
__global__ void __launch_bounds__(256) aggregate_kernel(
    const int* __restrict__ src, float* __restrict__ out)
{
    int warp = (blockIdx.x * blockDim.x + threadIdx.x) >> 5;
    int lane = threadIdx.x & 31;
    if (warp >= N_NODES) return;
    const int node = warp;

    const float4 q = *reinterpret_cast<const float4*>(&g_Q[node * 128 + lane * 4]);
    float4 acc = make_float4(0.f, 0.f, 0.f, 0.f);
    float  zz  = 0.f;

    const int beg = g_row_off[node];
    const int end = g_row_off[node + 1];
    for (int i = beg; i < end; ++i) {
        int e = g_eidx[i];
        int s = src[e];
        const float4 k4 = *reinterpret_cast<const float4*>(&g_K[s * 128 + lane * 4]);
        float p = q.x * k4.x + q.y * k4.y + q.z * k4.z + q.w * k4.w;
        p += __shfl_xor_sync(0xffffffffu, p, 1);
        p += __shfl_xor_sync(0xffffffffu, p, 2);
        float sc = p * 0.25f;                       // 1/sqrt(16)
        sc = fminf(fmaxf(sc, -5.f), 5.f);
        float w = __expf(sc);
        const float4 v4 = *reinterpret_cast<const float4*>(&g_V[s * 128 + lane * 4]);
        acc.x += v4.x * w;
        acc.y += v4.y * w;
        acc.z += v4.z * w;
        acc.w += v4.w * w;
        zz += w;                                    // same per quad-lane = z[head]
    }

    float inv = 1.f / (zz + 1e-6f);
    float4 o = make_float4(acc.x * inv, acc.y * inv, acc.z * inv, acc.w * inv);
    *reinterpret_cast<float4*>(&out[node * 128 + lane * 4]) = o;
}

// ---------------- launch ----------------
extern "C" void kernel_launch(void* const* d_in, const int* in_sizes, int n_in,
                              void* d_out, int out_size)
{
    const float* h   = (const float*)d_in[0];
    // d_in[1] (e), d_in[8] (We), d_in[9] (be) are unused by the reference output.
    const int*   src = (const int*)d_in[2];
    const int*   dst = (const int*)d_in[3];
    const float* Wq  = (const float*)d_in[4];
    const float* bq  = (const float*)d_in[5];
    const float* Wk  = (const float*)d_in[6];
    const float* bk  = (const float*)d_in[7];
    const float* Wv  = (const float*)d_in[10];
    const float* bv  = (const float*)d_in[11];
    float* out = (float*)d_out;

    dim3 gemm_grid((N_NODES + 63) / 64, 1, 3);
    gemm_qkv<<<gemm_grid, 256>>>(h, Wq, bq, Wk, bk, Wv, bv);

    zero_cnt_kernel<<<(N_NODES + 255) / 256, 256>>>();
    count_kernel<<<(N_EDGES + 255) / 256, 256>>>(dst);
    scan_kernel<<<1, 1024>>>();
    scatter_kernel<<<(N_EDGES + 255) / 256, 256>>>(dst);

    int agg_blocks = (N_NODES + 7) / 8;   // 8 warps (nodes) per 256-thread block
    aggregate_kernel<<<agg_blocks, 256>>>(src, out);
}

// round 2
// speedup vs baseline: 1.3113x; 1.3113x over previous
#include <cuda_runtime.h>

#define N_NODES 50000
#define N_EDGES 800000
#define CNT_BLOCKS 782          // matches gemm grid.x so count rides in grid z=0
#define SCAN_BLOCKS ((N_NODES + 255) / 256)   // 196

// ---------------- scratch (static __device__, zero-initialized at load) ----------------
__device__ float g_Q[N_NODES * 128];
__device__ float g_K[N_NODES * 128];
__device__ float g_V[N_NODES * 128];
__device__ int   g_row_off[N_NODES + 1];
__device__ int   g_cnt[N_NODES];      // counts -> cursors; re-zeroed by aggregate
__device__ int   g_esrc[N_EDGES];     // src node id per CSR slot
__device__ int   g_part[SCAN_BLOCKS];

// ---------------- fused QKV GEMM + edge count ----------------
// grid = (782, 1, 4): z==0 -> degree count (runs in first wave, hidden under GEMM)
//                     z in {1,2,3} -> C[z-1] = h @ W + b, BM=64,BN=128,BK=16.
__global__ void __launch_bounds__(256) gemm_qkv_count(
    const float* __restrict__ h, const int* __restrict__ dst,
    const float* __restrict__ Wq, const float* __restrict__ bq,
    const float* __restrict__ Wk, const float* __restrict__ bk,
    const float* __restrict__ Wv, const float* __restrict__ bv)
{
    const int z = blockIdx.z;
    if (z == 0) {
        int tid = blockIdx.x * 256 + threadIdx.x;
        for (int e = tid; e < N_EDGES; e += CNT_BLOCKS * 256)
            atomicAdd(&g_cnt[dst[e]], 1);
        return;
    }

    const float* W; const float* bias; float* C;
    if (z == 1)      { W = Wq; bias = bq; C = g_Q; }
    else if (z == 2) { W = Wk; bias = bk; C = g_K; }
    else             { W = Wv; bias = bv; C = g_V; }

    __shared__ float As[16][64];    // [k][m]
    __shared__ float Bs[16][128];   // [k][n]

    const int t    = threadIdx.x;
    const int row0 = blockIdx.x * 64;
    const int tidx = t & 15;        // col group (8 cols each)
    const int tidy = t >> 4;        // row group (4 rows each)

    float acc[4][8];
    #pragma unroll
    for (int i = 0; i < 4; i++)
        #pragma unroll
        for (int j = 0; j < 8; j++) acc[i][j] = 0.f;

    const int a_row = t >> 2;         // 0..63
    const int a_k   = (t & 3) * 4;    // 0,4,8,12
    const int b_row = t >> 5;         // 0..7
    const int b_col = (t & 31) * 4;   // 0..124

    for (int k0 = 0; k0 < 128; k0 += 16) {
        float4 av = make_float4(0.f, 0.f, 0.f, 0.f);
        int gr = row0 + a_row;
        if (gr < N_NODES)
            av = *reinterpret_cast<const float4*>(&h[gr * 128 + k0 + a_k]);
        As[a_k + 0][a_row] = av.x;
        As[a_k + 1][a_row] = av.y;
        As[a_k + 2][a_row] = av.z;
        As[a_k + 3][a_row] = av.w;

        float4 bv0 = *reinterpret_cast<const float4*>(&W[(k0 + b_row) * 128 + b_col]);
        float4 bv1 = *reinterpret_cast<const float4*>(&W[(k0 + 8 + b_row) * 128 + b_col]);
        *reinterpret_cast<float4*>(&Bs[b_row][b_col])     = bv0;
        *reinterpret_cast<float4*>(&Bs[b_row + 8][b_col]) = bv1;
        __syncthreads();

        #pragma unroll
        for (int k = 0; k < 16; k++) {
            float4 a4  = *reinterpret_cast<const float4*>(&As[k][tidy * 4]);
            float4 b40 = *reinterpret_cast<const float4*>(&Bs[k][tidx * 8]);
            float4 b41 = *reinterpret_cast<const float4*>(&Bs[k][tidx * 8 + 4]);
            float aa[4] = {a4.x, a4.y, a4.z, a4.w};
            float bb[8] = {b40.x, b40.y, b40.z, b40.w, b41.x, b41.y, b41.z, b41.w};
            #pragma unroll
            for (int i = 0; i < 4; i++)
                #pragma unroll
                for (int j = 0; j < 8; j++)
                    acc[i][j] += aa[i] * bb[j];
        }
        __syncthreads();
    }

    #pragma unroll
    for (int i = 0; i < 4; i++) {
        int gr = row0 + tidy * 4 + i;
        if (gr >= N_NODES) continue;
        #pragma unroll
        for (int j = 0; j < 8; j += 4) {
            int col = tidx * 8 + j;
            float4 o;
            o.x = acc[i][j + 0] + bias[col + 0];
            o.y = acc[i][j + 1] + bias[col + 1];
            o.z = acc[i][j + 2] + bias[col + 2];
            o.w = acc[i][j + 3] + bias[col + 3];
            *reinterpret_cast<float4*>(&C[gr * 128 + col]) = o;
        }
    }
}

// ---------------- parallel scan, stage 1: per-block (256-wide) sums ----------------
__global__ void __launch_bounds__(256) scan_part_kernel()
{
    __shared__ int ws[8];
    int gid = blockIdx.x * 256 + threadIdx.x;
    int v = (gid < N_NODES) ? g_cnt[gid] : 0;
    int s = __reduce_add_sync(0xffffffffu, v);
    if ((threadIdx.x & 31) == 0) ws[threadIdx.x >> 5] = s;
    __syncthreads();
    if (threadIdx.x == 0) {
        int tot = 0;
        #pragma unroll
        for (int j = 0; j < 8; j++) tot += ws[j];
        g_part[blockIdx.x] = tot;
    }
}

// ---------------- parallel scan, stage 2: block offset + intra-block exclusive scan ----------------
__global__ void __launch_bounds__(256) scan_final_kernel()
{
    __shared__ int ps[8];
    __shared__ int ws[8];
    const int t = threadIdx.x, b = blockIdx.x;
    const int lane = t & 31, w = t >> 5;

    // block offset = sum of preceding partials (SCAN_BLOCKS=196 <= 256)
    int pv = (t < b) ? g_part[t] : 0;
    int psum = __reduce_add_sync(0xffffffffu, pv);
    if (lane == 0) ps[w] = psum;
    __syncthreads();
    int offset = 0;
    #pragma unroll
    for (int j = 0; j < 8; j++) offset += ps[j];

    // intra-block exclusive scan of counts
    int gid = b * 256 + t;
    int c = (gid < N_NODES) ? g_cnt[gid] : 0;
    int incl = c;
    #pragma unroll
    for (int d = 1; d < 32; d <<= 1) {
        int u = __shfl_up_sync(0xffffffffu, incl, d);
        if (lane >= d) incl += u;
    }
    if (lane == 31) ws[w] = incl;
    __syncthreads();
    int woff = 0;
    #pragma unroll
    for (int j = 0; j < 8; j++) woff += (j < w) ? ws[j] : 0;

    int excl = offset + woff + incl - c;
    if (gid < N_NODES) {
        g_row_off[gid] = excl;
        g_cnt[gid]     = excl;           // cursor for scatter
    }
    if (gid == N_NODES - 1)
        g_row_off[N_NODES] = excl + c;
}

// ---------------- scatter: bucket src ids by dst ----------------
__global__ void __launch_bounds__(256) scatter_kernel(
    const int* __restrict__ src, const int* __restrict__ dst)
{
    int e = blockIdx.x * blockDim.x + threadIdx.x;
    if (e < N_EDGES) {
        int p = atomicAdd(&g_cnt[dst[e]], 1);
        g_esrc[p] = src[e];
    }
}

// ---------------- aggregation: one warp per dst node ----------------
// lane l owns columns 4l..4l+3; each 4-lane quad owns one head (D=16).
// Also restores g_cnt[node]=0 to keep the counter invariant for the next replay.
__global__ void __launch_bounds__(256) aggregate_kernel(float* __restrict__ out)
{
    int warp = (blockIdx.x * blockDim.x + threadIdx.x) >> 5;
    int lane = threadIdx.x & 31;
    if (warp >= N_NODES) return;
    const int node = warp;

    const float4 q = *reinterpret_cast<const float4*>(&g_Q[node * 128 + lane * 4]);
    float4 acc = make_float4(0.f, 0.f, 0.f, 0.f);
    float  zz  = 0.f;

    const int beg = g_row_off[node];
    const int end = g_row_off[node + 1];
    for (int i = beg; i < end; ++i) {
        int s = g_esrc[i];
        const float4 k4 = *reinterpret_cast<const float4*>(&g_K[s * 128 + lane * 4]);
        float p = q.x * k4.x + q.y * k4.y + q.z * k4.z + q.w * k4.w;
        p += __shfl_xor_sync(0xffffffffu, p, 1);
        p += __shfl_xor_sync(0xffffffffu, p, 2);
        float sc = p * 0.25f;                       // 1/sqrt(16)
        sc = fminf(fmaxf(sc, -5.f), 5.f);
        float wgt = __expf(sc);
        const float4 v4 = *reinterpret_cast<const float4*>(&g_V[s * 128 + lane * 4]);
        acc.x += v4.x * wgt;
        acc.y += v4.y * wgt;
        acc.z += v4.z * wgt;
        acc.w += v4.w * wgt;
        zz += wgt;                                  // same across quad = z[head]
    }

    float inv = 1.f / (zz + 1e-6f);
    float4 o = make_float4(acc.x * inv, acc.y * inv, acc.z * inv, acc.w * inv);
    *reinterpret_cast<float4*>(&out[node * 128 + lane * 4]) = o;

    if (lane == 0) g_cnt[node] = 0;                 // restore invariant for next launch
}

// ---------------- launch ----------------
extern "C" void kernel_launch(void* const* d_in, const int* in_sizes, int n_in,
                              void* d_out, int out_size)
{
    const float* h   = (const float*)d_in[0];
    // d_in[1] (e), d_in[8] (We), d_in[9] (be) are unused by the reference output.
    const int*   src = (const int*)d_in[2];
    const int*   dst = (const int*)d_in[3];
    const float* Wq  = (const float*)d_in[4];
    const float* bq  = (const float*)d_in[5];
    const float* Wk  = (const float*)d_in[6];
    const float* bk  = (const float*)d_in[7];
    const float* Wv  = (const float*)d_in[10];
    const float* bv  = (const float*)d_in[11];
    float* out = (float*)d_out;

    dim3 grid(CNT_BLOCKS, 1, 4);   // z=0: count, z=1..3: Q,K,V GEMM tiles
    gemm_qkv_count<<<grid, 256>>>(h, dst, Wq, bq, Wk, bk, Wv, bv);

    scan_part_kernel<<<SCAN_BLOCKS, 256>>>();
    scan_final_kernel<<<SCAN_BLOCKS, 256>>>();
    scatter_kernel<<<(N_EDGES + 255) / 256, 256>>>(src, dst);

    int agg_blocks = (N_NODES + 7) / 8;   // 8 warps (nodes) per 256-thread block
    aggregate_kernel<<<agg_blocks, 256>>>(out);
}